// round 8
// baseline (speedup 1.0000x reference)
#include <cuda_runtime.h>

#define W 512
#define H 512
#define NPLANES 96
#define SKEW 3
#define NWARPS 16          // one band (32 rows) per warp, whole plane per block
#define CH 16              // columns per chunk / round
#define NCHUNK 38          // ceil((512 + 3*31)=605 / 16)
#define D 7                // round offset per band link (producer 7 chunks ahead)
#define NROUNDS (NCHUNK + D * (NWARPS - 1))   // 143

// Floyd-Steinberg 1-bit error diffusion — bulk-synchronous wavefront.
// Block = one 512x512 plane, 16 warps; warp w owns rows [32w, 32w+32).
// In-warp: skew-3 anti-diagonal (lane l -> row 32w+l, col c = t-3l), err flows
// lane->lane via shfl_up with 2 steps of slack over the 26-cyc SHFL.
// Across warps: STATIC schedule. In round R, warp w runs chunk k = R - 7w.
// Producer chunk k+6 (all prevrow cols needed by consumer chunk k) completes
// at round k+7w-1, one barrier before the consumer uses it — dependence holds
// by construction. No polling, no flags: waiting warps sit in BAR stall and
// consume zero issue slots (R3-R7 lesson: spin polls were >50% of all issued
// instructions; nanosleep/mbarrier waits added per-link latency instead).
// __syncthreads() drains STS and orders SMEM natively — no fences needed.
__global__ void __launch_bounds__(NWARPS * 32, 1)
fs_dither_kernel(const float* __restrict__ x, float* __restrict__ out) {
    __shared__ float errbuf[NWARPS][W];
    __shared__ float zbuf[W];

    const int tid = threadIdx.x;
    const int w = tid >> 5;
    const int lane = tid & 31;
    const int plane = blockIdx.x;

    const float* __restrict__ xp = x + (size_t)plane * (H * W);
    float* __restrict__ op = out + (size_t)plane * (H * W);

    for (int i = tid; i < W; i += NWARPS * 32) zbuf[i] = 0.0f;
    __syncthreads();

    const float* __restrict__ prevrow = (w == 0) ? zbuf : errbuf[w - 1];
    float* __restrict__ myrow = errbuf[w];
    const int row = w * 32 + lane;
    const float* __restrict__ xrow = xp + (size_t)row * W;
    float* __restrict__ orow = op + (size_t)row * W;
    const bool is31 = (lane == 31);

    // Delay line: at step t lane l consumes e_ur=r2, e_u=r3, e_ul=r4 (row-above
    // errs at cols c+1, c, c-1); r1 is the 3-ahead value (lane0: prevrow[t+3]).
    float r1 = 0.0f, r2 = 0.0f, r3 = 0.0f, r4 = 0.0f;
    float left = 0.0f;

    for (int R = 0; R < NROUNDS; ++R) {
        const int k = R - D * w;
        if ((unsigned)k < (unsigned)NCHUNK) {
            int t = k * CH;

            if (k == 0 && lane == 0) {
                // Seed from prev row (producer wrote cols 0..2 six rounds ago;
                // zbuf for w==0). prev[-1] = 0 (pad).
                r4 = 0.0f;
                r3 = prevrow[0];
                r2 = prevrow[1];
                r1 = prevrow[2];
            }

            #pragma unroll 4
            for (int i = 0; i < CH; ++i, ++t) {
                const int c = t - SKEW * lane;
                const bool active = ((unsigned)c < (unsigned)W);
                const float e_ur = r2, e_u = r3, e_ul = r4;

                // Clamped-address load keeps inactive lanes branch-free.
                int cl = c < 0 ? 0 : (c > W - 1 ? W - 1 : c);
                float xv = __ldg(xrow + cl);

                // x = clip(x,-1,1); x01 = (x+1)/2  (exact, matches reference)
                xv = fminf(fmaxf(xv, -1.0f), 1.0f);
                float x01 = __fmul_rn(__fadd_rn(xv, 1.0f), 0.5f);

                // up = (1/16*e_ul + 5/16*e_u) + 3/16*e_ur (reference order)
                float u = __fadd_rn(__fadd_rn(__fmul_rn(0.0625f, e_ul),
                                              __fmul_rn(0.3125f, e_u)),
                                    __fmul_rn(0.1875f, e_ur));
                float pre = __fadd_rn(x01, u);
                float raw = __fadd_rn(pre, __fmul_rn(0.4375f, left));
                float val = fminf(fmaxf(raw, 0.0f), 1.0f);

                // q = round-half-even(val), val in [0,1]  <=>  raw > 0.5.
                // d = 0.5 - raw has exact sign (Sterbenz in [0.25,1]); tie->q=0.
                float d = __fadd_rn(0.5f, -raw);
                unsigned s = (unsigned)(__float_as_int(d) >> 31);
                // err = val - q exactly: val + (-1.0f masked); Sterbenz-exact.
                float err = __fadd_rn(val, __uint_as_float(s & 0xBF800000u));
                err = active ? err : 0.0f;   // inactive lanes feed zero padding

                // Single-statement guarded stores -> @P STG / @P STS (no BSSY).
                float ov = __uint_as_float(0xBF800000u ^ (s & 0x80000000u));
                if (active) orow[c] = ov;                  // output = 2q-1
                if (active & is31) myrow[c] = err;         // band handoff

                left = err;

                // Cross-lane propagation (2 steps of slack before consumption).
                float sh = __shfl_up_sync(0xFFFFFFFFu, err, 1);
                const int pi = t + SKEW;
                float pv = (pi < W) ? prevrow[pi] : 0.0f;  // broadcast LDS
                if (lane == 0) sh = pv;                    // SEL, no branch
                r4 = r3; r3 = r2; r2 = r1; r1 = sh;
            }
        }
        __syncthreads();   // round boundary: publishes this round's handoffs
    }
}

extern "C" void kernel_launch(void* const* d_in, const int* in_sizes, int n_in,
                              void* d_out, int out_size) {
    (void)in_sizes; (void)n_in; (void)out_size;
    const float* x = (const float*)d_in[0];
    float* out = (float*)d_out;
    fs_dither_kernel<<<NPLANES, NWARPS * 32>>>(x, out);
}

// round 9
// speedup vs baseline: 3.0553x; 3.0553x over previous
#include <cuda_runtime.h>

#define W 512
#define H 512
#define NPLANES 96
#define SKEW 2             // minimal skew: lane l -> col c = t - 2l
#define NWARPS 16          // one band (32 rows) per warp, whole plane per block
#define CH 16              // columns per sync chunk
#define LAG 64             // 31*SKEW + SKEW: producer lead needed by consumer
#define NSTEP_PAD 576      // 512 + 2*31 = 574, padded to 36 chunks of 16
#define NCHUNK 36
#define ROWPAD 640         // err rows padded with permanent zeros: prevrow[t+2]
                           // is unconditional for t <= 575 (max index 577)

// Floyd-Steinberg 1-bit error diffusion.
// Structure = R3 (best: 260us), with two deltas only:
//  (1) skew 3 -> 2: critical path 143 -> 111 chunks (-22.4%). The SHFL edge
//      (26 cyc) lands on the per-step chain, but measured step cost is ~216
//      cyc, so it is not binding.
//  (2) prev-row reads are unconditional LDS into zero-padded rows.
// Sync stays the proven volatile-spin chunk handoff (nanosleep, mbarrier and
// bulk-sync barriers all regressed: R4/R5/R8).
__global__ void __launch_bounds__(NWARPS * 32, 1)
fs_dither_kernel(const float* __restrict__ x, float* __restrict__ out) {
    __shared__ float errbuf[NWARPS][ROWPAD];
    __shared__ float zbuf[ROWPAD];
    __shared__ volatile unsigned progress[NWARPS];

    const int tid = threadIdx.x;
    const int w = tid >> 5;
    const int lane = tid & 31;
    const int plane = blockIdx.x;

    const float* __restrict__ xp = x + (size_t)plane * (H * W);
    float* __restrict__ op = out + (size_t)plane * (H * W);

    // Zero err rows INCLUDING pad columns (cols >= 512 are never rewritten).
    for (int i = tid; i < NWARPS * ROWPAD; i += NWARPS * 32)
        (&errbuf[0][0])[i] = 0.0f;
    for (int i = tid; i < ROWPAD; i += NWARPS * 32) zbuf[i] = 0.0f;
    if (tid < NWARPS) progress[tid] = 0u;
    __syncthreads();

    const float* __restrict__ prevrow = (w == 0) ? zbuf : errbuf[w - 1];
    float* __restrict__ myrow = errbuf[w];
    const int row = w * 32 + lane;
    const float* __restrict__ xrow = xp + (size_t)row * W;
    float* __restrict__ orow = op + (size_t)row * W;
    const bool is31 = (lane == 31);

    // Skew-2 delay line: at step t lane l consumes
    //   e_ur = r1  (row-above err at c+1; shfl'd at end of step t-1)
    //   e_u  = r2  (col c;   shfl'd at t-2)
    //   e_ul = r3  (col c-1; shfl'd at t-3)
    // Lane 0 substitutes prevrow[t+2] into the shfl each step.
    float r1 = 0.0f, r2 = 0.0f, r3 = 0.0f;
    float left = 0.0f;

    int t = 0;
    for (int k = 0; k < NCHUNK; ++k) {
        if (w != 0) {
            unsigned need = (unsigned)(t + CH + LAG);
            if (need > NSTEP_PAD) need = NSTEP_PAD;
            while (progress[w - 1] < need) { /* spin (proven fastest) */ }
        }
        __syncwarp();
        __threadfence_block();   // acquire: producer's STS now visible

        if (k == 0 && lane == 0) {
            // e_ul(t=0)=prev[-1]=0; e_u=prev[0]; e_ur=prev[1].
            r3 = 0.0f;
            r2 = prevrow[0];
            r1 = prevrow[1];
        }

        #pragma unroll 4
        for (int i = 0; i < CH; ++i, ++t) {
            const int c = t - SKEW * lane;
            const bool active = ((unsigned)c < (unsigned)W);
            const float e_ur = r1, e_u = r2, e_ul = r3;

            // Clamped-address load keeps inactive lanes branch-free (L1-hit).
            int cl = c < 0 ? 0 : (c > W - 1 ? W - 1 : c);
            float xv = __ldg(xrow + cl);

            // x = clip(x,-1,1); x01 = (x+1)/2  (exact, matches reference)
            xv = fminf(fmaxf(xv, -1.0f), 1.0f);
            float x01 = __fmul_rn(__fadd_rn(xv, 1.0f), 0.5f);

            // up = (1/16*e_ul + 5/16*e_u) + 3/16*e_ur  (reference order, no FMA)
            float u = __fadd_rn(__fadd_rn(__fmul_rn(0.0625f, e_ul),
                                          __fmul_rn(0.3125f, e_u)),
                                __fmul_rn(0.1875f, e_ur));
            float pre = __fadd_rn(x01, u);
            float raw = __fadd_rn(pre, __fmul_rn(0.4375f, left));
            float val = fminf(fmaxf(raw, 0.0f), 1.0f);

            // q = round-half-even(val), val in [0,1]  <=>  raw > 0.5.
            // d = 0.5 - raw has exact sign (Sterbenz in [0.25,1]); tie -> q=0.
            float d = __fadd_rn(0.5f, -raw);
            unsigned s = (unsigned)(__float_as_int(d) >> 31);
            // err = val - q exactly: val + (-1.0f masked); Sterbenz-exact.
            float err = __fadd_rn(val, __uint_as_float(s & 0xBF800000u));
            err = active ? err : 0.0f;   // inactive lanes feed zero padding

            // Single-statement guarded stores -> @P STG / @P STS (no BSSY).
            if (active) orow[c] = __uint_as_float(0xBF800000u ^ (s & 0x80000000u));
            if (active & is31) myrow[c] = err;   // band handoff

            left = err;

            // Cross-lane propagation; lane 0 injects the prev band's err.
            float sh = __shfl_up_sync(0xFFFFFFFFu, err, 1);
            float pv = prevrow[t + 2];           // unconditional bcast LDS (pad=0)
            if (lane == 0) sh = pv;              // SEL, no branch
            r3 = r2; r2 = r1; r1 = sh;
        }

        if (lane == 31) {
            __threadfence_block();     // release: STS before counter
            progress[w] = (unsigned)t;
        }
    }
}

extern "C" void kernel_launch(void* const* d_in, const int* in_sizes, int n_in,
                              void* d_out, int out_size) {
    (void)in_sizes; (void)n_in; (void)out_size;
    const float* x = (const float*)d_in[0];
    float* out = (float*)d_out;
    fs_dither_kernel<<<NPLANES, NWARPS * 32>>>(x, out);
}